// round 3
// baseline (speedup 1.0000x reference)
#include <cuda_runtime.h>
#include <cstddef>

// LIF forward, HBM-bound streaming formulation.
// B=16384 rows (independent recurrences), L=2048 timesteps (serial per row).
// out[0 : B*L]      = spikes (B,L) row-major
// out[B*L : 2*B*L]  = cumulative spike count series (B,L) row-major

#define LLEN   2048          // time length
#define RPB    64            // rows per block (== threads per block)
#define TPB    64
#define CCH    32            // time-chunk size
#define STRD   (RPB + 1)     // 65: padded stride for transposed tile -> conflict-free
#define NCHUNK (LLEN / CCH)  // 64
#define F4PT   (RPB * CCH / 4 / TPB)   // float4 loads per thread per chunk = 8

__global__ void __launch_bounds__(TPB)
lif_kernel(const float* __restrict__ I,
           float* __restrict__ outSpk,
           float* __restrict__ outNum)
{
    // Transposed tiles: element (t, r) at [t*STRD + r].
    __shared__ float A0[CCH * STRD];   // input / spike (in-place), buffer 0
    __shared__ float A1[CCH * STRD];   // input / spike (in-place), buffer 1
    __shared__ float SN[CCH * STRD];   // series (cumulative count)

    const int tid = threadIdx.x;
    const size_t rowBase = (size_t)blockIdx.x * RPB;
    const float* __restrict__ Ib = I      + rowBase * LLEN;
    float* __restrict__ Sb       = outSpk + rowBase * LLEN;
    float* __restrict__ Nb       = outNum + rowBase * LLEN;

    // Load mapping: idx = m*TPB + tid; local row lr = idx>>3, float4 col j = idx&7.
    // Global: 8-lane groups read 128B contiguous lines (fully coalesced).
    // STS bank = (4j+i)*65 + lr  (mod 32) = 4j + i + lr -> all 32 residues distinct.
    const int j  = tid & 7;
    const int lr0 = tid >> 3;

    float4 regs[F4PT];

    // ---- prefetch chunk 0 into registers, stage into A0 ----
    #pragma unroll
    for (int m = 0; m < F4PT; m++) {
        int lr = m * 8 + lr0;
        regs[m] = reinterpret_cast<const float4*>(Ib + (size_t)lr * LLEN)[j];
    }
    #pragma unroll
    for (int m = 0; m < F4PT; m++) {
        int lr = m * 8 + lr0;
        float4 x = regs[m];
        A0[(4*j+0)*STRD + lr] = x.x;
        A0[(4*j+1)*STRD + lr] = x.y;
        A0[(4*j+2)*STRD + lr] = x.z;
        A0[(4*j+3)*STRD + lr] = x.w;
    }
    __syncthreads();

    float v = 0.0f, a = 0.0f, snum = 0.0f;

    for (int k = 0; k < NCHUNK; k++) {
        float* __restrict__ Acur = (k & 1) ? A1 : A0;
        float* __restrict__ Anxt = (k & 1) ? A0 : A1;

        // ---- issue prefetch of chunk k+1 (overlaps with compute below) ----
        if (k + 1 < NCHUNK) {
            const float* __restrict__ src = Ib + (size_t)(k + 1) * CCH;
            #pragma unroll
            for (int m = 0; m < F4PT; m++) {
                int lr = m * 8 + lr0;
                regs[m] = reinterpret_cast<const float4*>(src + (size_t)lr * LLEN)[j];
            }
        }

        // ---- serial LIF over this chunk; thread tid owns row (rowBase+tid) ----
        // LDS bank = (t + tid) mod 32 -> conflict-free; spike overwrites input slot.
        #pragma unroll
        for (int t = 0; t < CCH; t++) {
            float Iv = Acur[t * STRD + tid];
            float th = 1.0f + 1.5f * a;          // uses OLD a (ref order)
            v = v - v * 0.05f + Iv;              // v += I - v/tau
            bool fired = (v >= th);
            float s = fired ? 1.0f : 0.0f;       // forward == hard spike exactly
            snum += s;
            Acur[t * STRD + tid] = s;            // spike out (in place)
            SN  [t * STRD + tid] = snum;         // series out
            v = fired ? -0.5f : v;               // detached reset (s in {0,1})
            a = a - a * 0.01f + s;               // a += s - a/tau_adapt
        }
        __syncthreads();

        // ---- coalesced store of spike + series tiles; stage next input tile ----
        {
            float* __restrict__ so = Sb + (size_t)k * CCH;
            float* __restrict__ no = Nb + (size_t)k * CCH;
            #pragma unroll
            for (int m = 0; m < F4PT; m++) {
                int lr = m * 8 + lr0;
                float4 sv, nv;
                sv.x = Acur[(4*j+0)*STRD + lr];
                sv.y = Acur[(4*j+1)*STRD + lr];
                sv.z = Acur[(4*j+2)*STRD + lr];
                sv.w = Acur[(4*j+3)*STRD + lr];
                nv.x = SN  [(4*j+0)*STRD + lr];
                nv.y = SN  [(4*j+1)*STRD + lr];
                nv.z = SN  [(4*j+2)*STRD + lr];
                nv.w = SN  [(4*j+3)*STRD + lr];
                reinterpret_cast<float4*>(so + (size_t)lr * LLEN)[j] = sv;
                reinterpret_cast<float4*>(no + (size_t)lr * LLEN)[j] = nv;
            }
            if (k + 1 < NCHUNK) {
                #pragma unroll
                for (int m = 0; m < F4PT; m++) {
                    int lr = m * 8 + lr0;
                    float4 x = regs[m];
                    Anxt[(4*j+0)*STRD + lr] = x.x;
                    Anxt[(4*j+1)*STRD + lr] = x.y;
                    Anxt[(4*j+2)*STRD + lr] = x.z;
                    Anxt[(4*j+3)*STRD + lr] = x.w;
                }
            }
        }
        __syncthreads();
    }
}

extern "C" void kernel_launch(void* const* d_in, const int* in_sizes, int n_in,
                              void* d_out, int out_size)
{
    const float* I = (const float*)d_in[0];
    const size_t total = (size_t)in_sizes[0];     // B * L
    const int B = (int)(total / LLEN);            // 16384

    float* outSpk = (float*)d_out;
    float* outNum = outSpk + total;

    dim3 grid(B / RPB);   // 256 blocks
    dim3 block(TPB);      // 64 threads
    lif_kernel<<<grid, block>>>(I, outSpk, outNum);
}

// round 4
// speedup vs baseline: 1.2802x; 1.2802x over previous
#include <cuda_runtime.h>
#include <cstddef>
#include <cstdint>

// Adaptive-LIF forward. B=16384 independent rows, L=2048 serial steps.
// out[0:B*L] = spikes, out[B*L:2BL] = cumulative spike counts. Row-major.
//
// Design: 512 single-warp CTAs, 32 rows/warp. Per 32-step chunk:
//   cp.async stages the chunk (coalesced) into a per-warp row-major tile
//   (stride 36 floats -> conflict-free .128 shared access, no transpose),
//   each thread pulls its row into registers, runs the recurrence in pure
//   register math, writes results through shared for coalesced STG.128.
// Only __syncwarp() — no CTA barriers anywhere.

#define LLEN   2048
#define CCH    32            // time-chunk
#define NCH    (LLEN / CCH)  // 64
#define STRIDE 36            // floats per tile row (pad: 36 mod 32 = 4 -> conflict-free .128)

__global__ void __launch_bounds__(32)
lif_kernel(const float* __restrict__ I,
           float* __restrict__ outSpk,
           float* __restrict__ outNum)
{
    __shared__ float IN0[32 * STRIDE];
    __shared__ float IN1[32 * STRIDE];
    __shared__ float SP [32 * STRIDE];
    __shared__ float SN [32 * STRIDE];

    const int lane = threadIdx.x;
    const size_t rowBase = (size_t)blockIdx.x * 32;
    const float* __restrict__ Ib = I      + rowBase * LLEN;
    float* __restrict__ Sb       = outSpk + rowBase * LLEN;
    float* __restrict__ Nb       = outNum + rowBase * LLEN;

    // Coalesced lane mapping: 8 lanes cover one row's 128B chunk segment.
    const int j   = lane & 7;   // float4 column within the 32-float chunk
    const int lr0 = lane >> 3;  // row group offset

    // ---- prefetch chunk 0 into IN0 via cp.async ----
    {
        #pragma unroll
        for (int m = 0; m < 8; m++) {
            const int lr = m * 4 + lr0;
            const float* g = Ib + (size_t)lr * LLEN + j * 4;
            const uint32_t s =
                (uint32_t)__cvta_generic_to_shared(&IN0[lr * STRIDE + j * 4]);
            asm volatile("cp.async.cg.shared.global [%0], [%1], 16;\n"
                         :: "r"(s), "l"(g));
        }
        asm volatile("cp.async.commit_group;\n");
    }

    float v = 0.0f, a = 0.0f, snum = 0.0f;
    float in[CCH], sn[CCH];
    float4* in4 = reinterpret_cast<float4*>(in);
    float4* sn4 = reinterpret_cast<float4*>(sn);

    for (int k = 0; k < NCH; k++) {
        float* __restrict__ INc = (k & 1) ? IN1 : IN0;
        float* __restrict__ INn = (k & 1) ? IN0 : IN1;

        // current chunk ready
        asm volatile("cp.async.wait_group 0;\n" ::: "memory");
        __syncwarp();

        // ---- row -> registers (conflict-free LDS.128, out of the chain) ----
        #pragma unroll
        for (int m = 0; m < 8; m++)
            in4[m] = *reinterpret_cast<const float4*>(&INc[lane * STRIDE + m * 4]);

        // ---- issue prefetch of chunk k+1 (hidden under compute+writeout) ----
        if (k + 1 < NCH) {
            const float* __restrict__ src = Ib + (size_t)(k + 1) * CCH;
            #pragma unroll
            for (int m = 0; m < 8; m++) {
                const int lr = m * 4 + lr0;
                const float* g = src + (size_t)lr * LLEN + j * 4;
                const uint32_t s =
                    (uint32_t)__cvta_generic_to_shared(&INn[lr * STRIDE + j * 4]);
                asm volatile("cp.async.cg.shared.global [%0], [%1], 16;\n"
                             :: "r"(s), "l"(g));
            }
            asm volatile("cp.async.commit_group;\n");
        }

        // ---- serial LIF, pure register math (exact R2 expressions) ----
        #pragma unroll
        for (int t = 0; t < CCH; t++) {
            const float Iv = in[t];
            const float th = 1.0f + 1.5f * a;   // OLD a (ref order)
            v = v - v * 0.05f + Iv;             // v += I - v/tau
            const bool fired = (v >= th);
            const float s = fired ? 1.0f : 0.0f;
            snum += s;
            in[t] = s;                          // spike overwrites input reg
            sn[t] = snum;
            v = fired ? -0.5f : v;              // detached reset
            a = a - a * 0.01f + s;              // a += s - a/tau_adapt
        }

        // ---- results -> shared (conflict-free STS.128) ----
        #pragma unroll
        for (int m = 0; m < 8; m++) {
            *reinterpret_cast<float4*>(&SP[lane * STRIDE + m * 4]) = in4[m];
            *reinterpret_cast<float4*>(&SN[lane * STRIDE + m * 4]) = sn4[m];
        }
        __syncwarp();

        // ---- coalesced gather + STG.128 ----
        float* __restrict__ so = Sb + (size_t)k * CCH;
        float* __restrict__ no = Nb + (size_t)k * CCH;
        #pragma unroll
        for (int m = 0; m < 8; m++) {
            const int lr = m * 4 + lr0;
            const float4 sv = *reinterpret_cast<const float4*>(&SP[lr * STRIDE + j * 4]);
            const float4 nv = *reinterpret_cast<const float4*>(&SN[lr * STRIDE + j * 4]);
            *reinterpret_cast<float4*>(so + (size_t)lr * LLEN + j * 4) = sv;
            *reinterpret_cast<float4*>(no + (size_t)lr * LLEN + j * 4) = nv;
        }
        // next iteration's top __syncwarp orders these LDS against the next STS
    }
}

extern "C" void kernel_launch(void* const* d_in, const int* in_sizes, int n_in,
                              void* d_out, int out_size)
{
    const float* I = (const float*)d_in[0];
    const size_t total = (size_t)in_sizes[0];   // B * L
    const int B = (int)(total / LLEN);          // 16384

    float* outSpk = (float*)d_out;
    float* outNum = outSpk + total;

    lif_kernel<<<B / 32, 32>>>(I, outSpk, outNum);  // 512 single-warp CTAs
}

// round 5
// speedup vs baseline: 1.2829x; 1.0021x over previous
#include <cuda_runtime.h>
#include <cstddef>
#include <cstdint>

// Adaptive-LIF forward. B=16384 independent rows, L=2048 serial steps.
// out[0:B*L] = spikes, out[B*L:2BL] = cumulative spike counts. Row-major.
//
// Design: 512 single-warp CTAs, 32 rows/warp. Per 32-step chunk:
//   cp.async stages the chunk (coalesced) into a per-warp row-major tile
//   (stride 36 floats -> conflict-free .128 shared access, no transpose),
//   each thread pulls its row into registers, runs the recurrence in pure
//   register math, writes results through shared for coalesced STG.128.
// Only __syncwarp() — no CTA barriers anywhere.

#define LLEN   2048
#define CCH    32            // time-chunk
#define NCH    (LLEN / CCH)  // 64
#define STRIDE 36            // floats per tile row (pad: 36 mod 32 = 4 -> conflict-free .128)

__global__ void __launch_bounds__(32)
lif_kernel(const float* __restrict__ I,
           float* __restrict__ outSpk,
           float* __restrict__ outNum)
{
    __shared__ float IN0[32 * STRIDE];
    __shared__ float IN1[32 * STRIDE];
    __shared__ float SP [32 * STRIDE];
    __shared__ float SN [32 * STRIDE];

    const int lane = threadIdx.x;
    const size_t rowBase = (size_t)blockIdx.x * 32;
    const float* __restrict__ Ib = I      + rowBase * LLEN;
    float* __restrict__ Sb       = outSpk + rowBase * LLEN;
    float* __restrict__ Nb       = outNum + rowBase * LLEN;

    // Coalesced lane mapping: 8 lanes cover one row's 128B chunk segment.
    const int j   = lane & 7;   // float4 column within the 32-float chunk
    const int lr0 = lane >> 3;  // row group offset

    // ---- prefetch chunk 0 into IN0 via cp.async ----
    {
        #pragma unroll
        for (int m = 0; m < 8; m++) {
            const int lr = m * 4 + lr0;
            const float* g = Ib + (size_t)lr * LLEN + j * 4;
            const uint32_t s =
                (uint32_t)__cvta_generic_to_shared(&IN0[lr * STRIDE + j * 4]);
            asm volatile("cp.async.cg.shared.global [%0], [%1], 16;\n"
                         :: "r"(s), "l"(g));
        }
        asm volatile("cp.async.commit_group;\n");
    }

    float v = 0.0f, a = 0.0f, snum = 0.0f;
    float in[CCH], sn[CCH];
    float4* in4 = reinterpret_cast<float4*>(in);
    float4* sn4 = reinterpret_cast<float4*>(sn);

    for (int k = 0; k < NCH; k++) {
        float* __restrict__ INc = (k & 1) ? IN1 : IN0;
        float* __restrict__ INn = (k & 1) ? IN0 : IN1;

        // current chunk ready
        asm volatile("cp.async.wait_group 0;\n" ::: "memory");
        __syncwarp();

        // ---- row -> registers (conflict-free LDS.128, out of the chain) ----
        #pragma unroll
        for (int m = 0; m < 8; m++)
            in4[m] = *reinterpret_cast<const float4*>(&INc[lane * STRIDE + m * 4]);

        // ---- issue prefetch of chunk k+1 (hidden under compute+writeout) ----
        if (k + 1 < NCH) {
            const float* __restrict__ src = Ib + (size_t)(k + 1) * CCH;
            #pragma unroll
            for (int m = 0; m < 8; m++) {
                const int lr = m * 4 + lr0;
                const float* g = src + (size_t)lr * LLEN + j * 4;
                const uint32_t s =
                    (uint32_t)__cvta_generic_to_shared(&INn[lr * STRIDE + j * 4]);
                asm volatile("cp.async.cg.shared.global [%0], [%1], 16;\n"
                             :: "r"(s), "l"(g));
            }
            asm volatile("cp.async.commit_group;\n");
        }

        // ---- serial LIF, pure register math (exact R2 expressions) ----
        #pragma unroll
        for (int t = 0; t < CCH; t++) {
            const float Iv = in[t];
            const float th = 1.0f + 1.5f * a;   // OLD a (ref order)
            v = v - v * 0.05f + Iv;             // v += I - v/tau
            const bool fired = (v >= th);
            const float s = fired ? 1.0f : 0.0f;
            snum += s;
            in[t] = s;                          // spike overwrites input reg
            sn[t] = snum;
            v = fired ? -0.5f : v;              // detached reset
            a = a - a * 0.01f + s;              // a += s - a/tau_adapt
        }

        // ---- results -> shared (conflict-free STS.128) ----
        #pragma unroll
        for (int m = 0; m < 8; m++) {
            *reinterpret_cast<float4*>(&SP[lane * STRIDE + m * 4]) = in4[m];
            *reinterpret_cast<float4*>(&SN[lane * STRIDE + m * 4]) = sn4[m];
        }
        __syncwarp();

        // ---- coalesced gather + STG.128 ----
        float* __restrict__ so = Sb + (size_t)k * CCH;
        float* __restrict__ no = Nb + (size_t)k * CCH;
        #pragma unroll
        for (int m = 0; m < 8; m++) {
            const int lr = m * 4 + lr0;
            const float4 sv = *reinterpret_cast<const float4*>(&SP[lr * STRIDE + j * 4]);
            const float4 nv = *reinterpret_cast<const float4*>(&SN[lr * STRIDE + j * 4]);
            *reinterpret_cast<float4*>(so + (size_t)lr * LLEN + j * 4) = sv;
            *reinterpret_cast<float4*>(no + (size_t)lr * LLEN + j * 4) = nv;
        }
        // next iteration's top __syncwarp orders these LDS against the next STS
    }
}

extern "C" void kernel_launch(void* const* d_in, const int* in_sizes, int n_in,
                              void* d_out, int out_size)
{
    const float* I = (const float*)d_in[0];
    const size_t total = (size_t)in_sizes[0];   // B * L
    const int B = (int)(total / LLEN);          // 16384

    float* outSpk = (float*)d_out;
    float* outNum = outSpk + total;

    lif_kernel<<<B / 32, 32>>>(I, outSpk, outNum);  // 512 single-warp CTAs
}